// round 2
// baseline (speedup 1.0000x reference)
#include <cuda_runtime.h>
#include <cstdint>
#include <cstddef>

// Problem constants (fixed by the dataset)
#define N_ROWS_MAX 1000000
#define NLOCS      100000
#define NTIMES     169
#define NUSERS1    50001
#define HMAX       (NLOCS * NTIMES)          // 16,900,000 hash-space upper bound
#define NW         ((HMAX + 31) / 32)        // 528,125 bitmap words
#define TILE_H     8192                      // hashes per tile (256 words)
#define NTILES     ((HMAX + TILE_H - 1) / TILE_H)  // 2063
#define CMASK      0x03FFFFFFu               // low 26 bits: sum of user ids

// ---------------- device scratch (static; no allocations allowed) ----------
__device__ unsigned d_cnt[HMAX];                       // packed: (count<<26)|sum_u
__device__ unsigned d_wordPrefix[NW];                  // exclusive presence prefix per 32-hash word
__device__ unsigned d_partials[NTILES];                // per-tile presence sums -> exclusive offsets
__device__ int      d_gh[N_ROWS_MAX];                  // groupHash[g]
__device__ unsigned d_gv[N_ROWS_MAX];                  // packed cnt word per group
__device__ float    d_usum[(size_t)N_ROWS_MAX * 32];   // per-group user-emb sum (multi groups only)
__device__ float    d_A[(size_t)NLOCS * 128];          // W_loc @ loc_emb[x]
__device__ float    d_B[NTIMES * 128];                 // W_time @ time_emb[t]
__device__ float    d_C[(size_t)NUSERS1 * 128];        // W_user @ user_emb[u]
__device__ int      d_M1;                              // max(x)
__device__ unsigned d_nuniq;

// ---------------- K0: zero cnt + scalars ----------------
__global__ void k_zero_cnt() {
    size_t i = (size_t)blockIdx.x * blockDim.x + threadIdx.x;
    const size_t n4 = HMAX / 4;   // HMAX divisible by 4
    if (i < n4) ((uint4*)d_cnt)[i] = make_uint4(0, 0, 0, 0);
    if (i == 0) d_M1 = 0;
}

// ---------------- K1: max(x) ----------------
__global__ void k_max(const int* __restrict__ x, int n) {
    int v = 0;
    for (int i = blockIdx.x * blockDim.x + threadIdx.x; i < n; i += gridDim.x * blockDim.x)
        v = max(v, x[i]);
    #pragma unroll
    for (int o = 16; o; o >>= 1) v = max(v, __shfl_xor_sync(0xffffffffu, v, o));
    if ((threadIdx.x & 31) == 0) atomicMax(&d_M1, v);
}

// ---------------- K2: count + pack user id ----------------
__global__ void k_count(const int* __restrict__ x, const int* __restrict__ t,
                        const int* __restrict__ u, int n) {
    int i = blockIdx.x * blockDim.x + threadIdx.x;
    if (i >= n) return;
    int M = d_M1 + 1;
    int h = t[i] * M + x[i];
    atomicAdd(&d_cnt[h], (1u << 26) | (unsigned)u[i]);
}

// ---------------- K3: per-tile presence sums ----------------
__global__ void k_tilesum() {
    __shared__ unsigned sred[256];
    size_t base = (size_t)blockIdx.x * TILE_H;
    unsigned s = 0;
    for (int it = 0; it < 32; it++) {
        size_t idx = base + (size_t)it * 256 + threadIdx.x;
        if (idx < HMAX) s += (d_cnt[idx] != 0);
    }
    sred[threadIdx.x] = s;
    __syncthreads();
    for (int o = 128; o; o >>= 1) {
        if (threadIdx.x < o) sred[threadIdx.x] += sred[threadIdx.x + o];
        __syncthreads();
    }
    if (threadIdx.x == 0) d_partials[blockIdx.x] = sred[0];
}

// ---------------- K4: single-block exclusive scan of tile sums ----------------
__global__ void k_scan() {
    __shared__ unsigned sh[1024];
    unsigned carry = 0;
    int tid = threadIdx.x;
    for (int base = 0; base < NTILES; base += 1024) {
        int i = base + tid;
        unsigned v = (i < NTILES) ? d_partials[i] : 0;
        sh[tid] = v;
        __syncthreads();
        for (int o = 1; o < 1024; o <<= 1) {
            unsigned a = (tid >= o) ? sh[tid - o] : 0;
            __syncthreads();
            sh[tid] += a;
            __syncthreads();
        }
        if (i < NTILES) d_partials[i] = carry + sh[tid] - v;  // exclusive
        unsigned tot = sh[1023];
        __syncthreads();
        carry += tot;
    }
    if (tid == 0) d_nuniq = carry;
}

// ---------------- K5: emit word prefixes, group table, zero multi usum ------
__global__ void k_emit() {
    __shared__ unsigned sv[TILE_H];
    __shared__ unsigned wsum[256];
    int tid = threadIdx.x;
    size_t base = (size_t)blockIdx.x * TILE_H;
    for (int it = 0; it < 32; it++) {
        size_t idx = base + (size_t)it * 256 + tid;
        sv[it * 256 + tid] = (idx < HMAX) ? d_cnt[idx] : 0;
    }
    __syncthreads();
    // rotated reads -> conflict-free; build ordered bit masks
    unsigned mask = 0, mmask = 0;
    #pragma unroll
    for (int kk = 0; kk < 32; kk++) {
        int j = (kk + tid) & 31;
        unsigned v = sv[tid * 32 + j];
        if (v) mask |= 1u << j;
        if ((v >> 26) >= 2) mmask |= 1u << j;
    }
    unsigned pc = __popc(mask);
    wsum[tid] = pc;
    __syncthreads();
    for (int o = 1; o < 256; o <<= 1) {
        unsigned a = (tid >= o) ? wsum[tid - o] : 0;
        __syncthreads();
        wsum[tid] += a;
        __syncthreads();
    }
    unsigned off = d_partials[blockIdx.x] + wsum[tid] - pc;
    int w = blockIdx.x * 256 + tid;
    if (w < NW) d_wordPrefix[w] = off;
    while (mask) {
        int j = __ffs(mask) - 1;
        mask &= mask - 1;
        unsigned v = sv[tid * 32 + j];
        d_gh[off] = (int)(base + tid * 32 + j);
        d_gv[off] = v;
        if (mmask & (1u << j)) {
            float4 z = make_float4(0.f, 0.f, 0.f, 0.f);
            float4* p = (float4*)&d_usum[(size_t)off * 32];
            #pragma unroll
            for (int q = 0; q < 8; q++) p[q] = z;
        }
        off++;
    }
}

// ---------------- K6: accumulate user-emb sums for multi-count rows --------
__global__ void k_accum(const int* __restrict__ x, const int* __restrict__ t,
                        const int* __restrict__ u, const float* __restrict__ user_emb,
                        int n) {
    int i = blockIdx.x * blockDim.x + threadIdx.x;
    if (i >= n) return;
    int M = d_M1 + 1;
    int h = t[i] * M + x[i];
    unsigned v = d_cnt[h];
    if ((v >> 26) < 2) return;   // singleton handled via packed user id
    int w = h >> 5, r = h & 31;
    unsigned g = d_wordPrefix[w];
    for (int k = 0; k < r; k++) g += (d_cnt[(w << 5) + k] != 0);
    const float* ue = user_emb + (size_t)u[i] * 32;
    float* us = &d_usum[(size_t)g * 32];
    #pragma unroll 8
    for (int d2 = 0; d2 < 32; d2++) atomicAdd(&us[d2], ue[d2]);
}

// ---------------- precompute kernels ----------------
__global__ void kp_B(const float* __restrict__ W, const float* __restrict__ time_emb) {
    int t = blockIdx.x, d = threadIdx.x;
    float acc = 0.f;
    #pragma unroll
    for (int k = 0; k < 32; k++) acc += W[d * 128 + 64 + k] * time_emb[t * 32 + k];
    d_B[t * 128 + d] = acc;
}

__global__ void kp_C(const float* __restrict__ W, const float* __restrict__ user_emb) {
    int uu = blockIdx.x, d = threadIdx.x;
    float acc = 0.f;
    #pragma unroll
    for (int k = 0; k < 32; k++) acc += W[d * 128 + 96 + k] * user_emb[(size_t)uu * 32 + k];
    d_C[(size_t)uu * 128 + d] = acc;
}

// A[x] = W_loc @ loc_emb[x]; 32 loc rows per 128-thread block
__global__ void kp_A(const float* __restrict__ W, const float* __restrict__ loc_emb) {
    __shared__ float  Wt[64][129];      // transposed W_loc, padded (conflict-free)
    __shared__ float4 loc4[32][16];     // 32 rows x 64 floats
    int tid = threadIdx.x;
    for (int it = 0; it < 64; it++) {
        int i = it * 128 + tid;
        int d = i >> 6, k = i & 63;
        Wt[k][d] = W[d * 128 + k];
    }
    size_t rbase = (size_t)blockIdx.x * 32;
    for (int it = 0; it < 16; it++) {
        int i = it * 128 + tid;
        int r = i >> 6, k = i & 63;
        ((float*)loc4)[r * 64 + k] = loc_emb[(rbase + r) * 64 + k];
    }
    __syncthreads();
    int d = tid;
    for (int rb = 0; rb < 4; rb++) {
        float acc[8] = {0, 0, 0, 0, 0, 0, 0, 0};
        #pragma unroll
        for (int k4 = 0; k4 < 16; k4++) {
            float w0 = Wt[k4 * 4 + 0][d], w1 = Wt[k4 * 4 + 1][d];
            float w2 = Wt[k4 * 4 + 2][d], w3 = Wt[k4 * 4 + 3][d];
            #pragma unroll
            for (int r8 = 0; r8 < 8; r8++) {
                float4 lv = loc4[rb * 8 + r8][k4];
                acc[r8] += w0 * lv.x + w1 * lv.y + w2 * lv.z + w3 * lv.w;
            }
        }
        #pragma unroll
        for (int r8 = 0; r8 < 8; r8++)
            d_A[(rbase + rb * 8 + r8) * 128 + d] = acc[r8];
    }
}

// ---------------- K7: final output ----------------
__device__ __forceinline__ float ftanh(float v) {
    float a = fabsf(v);
    if (a < 0.5f) {
        float s = v * v;
        return v * (1.f + s * (-0.333333333f + s * (0.133333333f + s * (-0.053968254f))));
    }
    return tanhf(v);
}

__global__ void k_out(const float* __restrict__ W, const float* __restrict__ bias,
                      float* __restrict__ out, int n) {
    int warp = (int)((blockIdx.x * blockDim.x + threadIdx.x) >> 5);
    int lane = threadIdx.x & 31;
    if (warp >= n) return;
    float4* o4 = (float4*)(out + (size_t)warp * 128) + lane;
    unsigned nu = d_nuniq;
    if ((unsigned)warp >= nu) {
        __stcs(o4, make_float4(0.f, 0.f, 0.f, 0.f));
        return;
    }
    int h = d_gh[warp];
    unsigned v = d_gv[warp];
    unsigned c = v >> 26;
    int M = d_M1 + 1;
    int xx = h % M, tt = h / M;
    float4 a  = *(const float4*)&d_A[(size_t)xx * 128 + lane * 4];
    float4 bt = *(const float4*)&d_B[tt * 128 + lane * 4];
    float4 bi = *(const float4*)&bias[lane * 4];
    float4 uc;
    if (c == 1) {
        unsigned uu = v & CMASK;
        uc = *(const float4*)&d_C[(size_t)uu * 128 + lane * 4];
    } else {
        float inv = 1.f / (float)c;
        float um = d_usum[(size_t)warp * 32 + lane] * inv;
        float a0 = 0, a1 = 0, a2 = 0, a3 = 0;
        int dbase = lane * 4;
        #pragma unroll
        for (int k = 0; k < 32; k++) {
            float umk = __shfl_sync(0xffffffffu, um, k);
            a0 += W[(dbase + 0) * 128 + 96 + k] * umk;
            a1 += W[(dbase + 1) * 128 + 96 + k] * umk;
            a2 += W[(dbase + 2) * 128 + 96 + k] * umk;
            a3 += W[(dbase + 3) * 128 + 96 + k] * umk;
        }
        uc = make_float4(a0, a1, a2, a3);
    }
    float4 r;
    r.x = ftanh(a.x + bt.x + uc.x + bi.x);
    r.y = ftanh(a.y + bt.y + uc.y + bi.y);
    r.z = ftanh(a.z + bt.z + uc.z + bi.z);
    r.w = ftanh(a.w + bt.w + uc.w + bi.w);
    __stcs(o4, r);
}

// ---------------- host launch ----------------
extern "C" void kernel_launch(void* const* d_in, const int* in_sizes, int n_in,
                              void* d_out, int out_size) {
    const float* loc_emb  = (const float*)d_in[0];
    const float* time_emb = (const float*)d_in[1];
    const float* user_emb = (const float*)d_in[2];
    const float* W        = (const float*)d_in[3];
    const float* b        = (const float*)d_in[4];
    const int*   x        = (const int*)d_in[5];
    const int*   t        = (const int*)d_in[6];
    const int*   u        = (const int*)d_in[7];
    int n       = in_sizes[5];              // 1,000,000 rows
    int nUsers1 = in_sizes[2] / 32;         // 50,001
    int rows    = out_size / 128;           // output rows (== n)

    k_zero_cnt<<<(HMAX / 4 + 255) / 256, 256>>>();
    k_max<<<512, 256>>>(x, n);
    k_count<<<(n + 255) / 256, 256>>>(x, t, u, n);
    k_tilesum<<<NTILES, 256>>>();
    k_scan<<<1, 1024>>>();
    k_emit<<<NTILES, 256>>>();
    k_accum<<<(n + 255) / 256, 256>>>(x, t, u, user_emb, n);
    // precomputes last so A/C stay hot in L2 for k_out
    kp_B<<<NTIMES, 128>>>(W, time_emb);
    kp_C<<<nUsers1, 128>>>(W, user_emb);
    kp_A<<<NLOCS / 32, 128>>>(W, loc_emb);
    k_out<<<(rows * 32 + 255) / 256, 256>>>(W, b, (float*)d_out, rows);
}

// round 3
// speedup vs baseline: 1.0826x; 1.0826x over previous
#include <cuda_runtime.h>
#include <cuda_fp16.h>
#include <cstdint>
#include <cstddef>

// Problem constants (fixed by the dataset)
#define N_ROWS_MAX 1000000
#define NLOCS      100000
#define NTIMES     169
#define NUSERS1    50001
#define MCONST     100000u                   // hash multiplier: any M > max(x) gives identical ordering
#define HMAX       (NLOCS * NTIMES)          // 16,900,000 hash-space upper bound
#define TILE_H     8192                      // hashes per tile (256 words of 32)
#define NTILES     ((HMAX + TILE_H - 1) / TILE_H)  // 2063
#define CMASK      0x03FFFFFFu               // low 26 bits

// ---------------- device scratch (static; no allocations allowed) ----------
__device__ unsigned d_cnt[HMAX];                       // packed: (count<<26)|sum_u  (multi: |group_id)
__device__ unsigned d_partials[NTILES];                // per-tile presence sums -> exclusive offsets
__device__ uint2    d_g2[N_ROWS_MAX];                  // (hash, packed cnt word) per group
__device__ float    d_usum[(size_t)N_ROWS_MAX * 32];   // per-group user-emb sum (multi groups only)
__device__ __half   d_Ah[(size_t)NLOCS * 128];         // fp16: W_loc @ loc_emb[x]      (25.6 MB)
__device__ float    d_Bb[NTIMES * 128];                // fp32: W_time @ time_emb[t] + bias (tiny)
__device__ __half   d_Ch[(size_t)NUSERS1 * 128];       // fp16: W_user @ user_emb[u]    (12.8 MB)
__device__ unsigned d_nuniq;

// ---------------- K0: zero cnt ----------------
__global__ void k_zero_cnt() {
    size_t i = (size_t)blockIdx.x * blockDim.x + threadIdx.x;
    const size_t n4 = HMAX / 4;
    if (i < n4) ((uint4*)d_cnt)[i] = make_uint4(0, 0, 0, 0);
}

// ---------------- K1: count + pack user id ----------------
__global__ void k_count(const int* __restrict__ x, const int* __restrict__ t,
                        const int* __restrict__ u, int n) {
    int i = blockIdx.x * blockDim.x + threadIdx.x;
    if (i >= n) return;
    unsigned h = (unsigned)t[i] * MCONST + (unsigned)x[i];
    atomicAdd(&d_cnt[h], (1u << 26) | (unsigned)u[i]);
}

// ---------------- K2: per-tile presence sums ----------------
__global__ void k_tilesum() {
    __shared__ unsigned sred[256];
    size_t base = (size_t)blockIdx.x * TILE_H;
    unsigned s = 0;
    #pragma unroll 8
    for (int it = 0; it < 32; it++) {
        size_t idx = base + (size_t)it * 256 + threadIdx.x;
        if (idx < HMAX) s += (d_cnt[idx] != 0);
    }
    sred[threadIdx.x] = s;
    __syncthreads();
    for (int o = 128; o; o >>= 1) {
        if (threadIdx.x < o) sred[threadIdx.x] += sred[threadIdx.x + o];
        __syncthreads();
    }
    if (threadIdx.x == 0) d_partials[blockIdx.x] = sred[0];
}

// ---------------- K3: single-block exclusive scan of tile sums --------------
__global__ void k_scan() {
    __shared__ unsigned sh[1024];
    unsigned carry = 0;
    int tid = threadIdx.x;
    for (int base = 0; base < NTILES; base += 1024) {
        int i = base + tid;
        unsigned v = (i < NTILES) ? d_partials[i] : 0;
        sh[tid] = v;
        __syncthreads();
        for (int o = 1; o < 1024; o <<= 1) {
            unsigned a = (tid >= o) ? sh[tid - o] : 0;
            __syncthreads();
            sh[tid] += a;
            __syncthreads();
        }
        if (i < NTILES) d_partials[i] = carry + sh[tid] - v;  // exclusive
        unsigned tot = sh[1023];
        __syncthreads();
        carry += tot;
    }
    if (tid == 0) d_nuniq = carry;
}

// ---------------- K4: emit group table; tag multi slots with group id -------
__global__ void k_emit() {
    __shared__ unsigned sv[TILE_H];
    __shared__ unsigned wsum[256];
    int tid = threadIdx.x;
    size_t base = (size_t)blockIdx.x * TILE_H;
    for (int it = 0; it < 32; it++) {
        size_t idx = base + (size_t)it * 256 + tid;
        sv[it * 256 + tid] = (idx < HMAX) ? d_cnt[idx] : 0;
    }
    __syncthreads();
    // rotated reads -> conflict-free; build ordered bit masks
    unsigned mask = 0, mmask = 0;
    #pragma unroll
    for (int kk = 0; kk < 32; kk++) {
        int j = (kk + tid) & 31;
        unsigned v = sv[tid * 32 + j];
        if (v) mask |= 1u << j;
        if ((v >> 26) >= 2) mmask |= 1u << j;
    }
    unsigned pc = __popc(mask);
    wsum[tid] = pc;
    __syncthreads();
    for (int o = 1; o < 256; o <<= 1) {
        unsigned a = (tid >= o) ? wsum[tid - o] : 0;
        __syncthreads();
        wsum[tid] += a;
        __syncthreads();
    }
    unsigned off = d_partials[blockIdx.x] + wsum[tid] - pc;
    while (mask) {
        int j = __ffs(mask) - 1;
        mask &= mask - 1;
        unsigned v = sv[tid * 32 + j];
        size_t idx = base + (size_t)tid * 32 + j;
        d_g2[off] = make_uint2((unsigned)idx, v);
        if (mmask & (1u << j)) {
            // overwrite low bits of cnt slot with group id for O(1) accum lookup
            d_cnt[idx] = (v & ~CMASK) | off;
            float4 z = make_float4(0.f, 0.f, 0.f, 0.f);
            float4* p = (float4*)&d_usum[(size_t)off * 32];
            #pragma unroll
            for (int q = 0; q < 8; q++) p[q] = z;
        }
        off++;
    }
}

// ---------------- K5: accumulate user-emb sums for multi-count rows --------
__global__ void k_accum(const int* __restrict__ x, const int* __restrict__ t,
                        const int* __restrict__ u, const float* __restrict__ user_emb,
                        int n) {
    int i = blockIdx.x * blockDim.x + threadIdx.x;
    if (i >= n) return;
    unsigned h = (unsigned)t[i] * MCONST + (unsigned)x[i];
    unsigned v = d_cnt[h];
    if ((v >> 26) < 2) return;        // singleton handled via packed user id
    unsigned g = v & CMASK;           // group id written by k_emit
    const float* ue = user_emb + (size_t)u[i] * 32;
    float* us = &d_usum[(size_t)g * 32];
    #pragma unroll 8
    for (int d2 = 0; d2 < 32; d2++) atomicAdd(&us[d2], ue[d2]);
}

// ---------------- precompute kernels ----------------
__global__ void kp_B(const float* __restrict__ W, const float* __restrict__ time_emb,
                     const float* __restrict__ bias) {
    int t = blockIdx.x, d = threadIdx.x;
    float acc = bias[d];
    #pragma unroll
    for (int k = 0; k < 32; k++) acc += W[d * 128 + 64 + k] * time_emb[t * 32 + k];
    d_Bb[t * 128 + d] = acc;
}

__global__ void kp_C(const float* __restrict__ W, const float* __restrict__ user_emb) {
    int uu = blockIdx.x, d = threadIdx.x;
    float acc = 0.f;
    #pragma unroll
    for (int k = 0; k < 32; k++) acc += W[d * 128 + 96 + k] * user_emb[(size_t)uu * 32 + k];
    d_Ch[(size_t)uu * 128 + d] = __float2half_rn(acc);
}

// A[x] = W_loc @ loc_emb[x]; 32 loc rows per 128-thread block
__global__ void kp_A(const float* __restrict__ W, const float* __restrict__ loc_emb) {
    __shared__ float  Wt[64][129];      // transposed W_loc, padded (conflict-free)
    __shared__ float4 loc4[32][16];     // 32 rows x 64 floats
    int tid = threadIdx.x;
    for (int it = 0; it < 64; it++) {
        int i = it * 128 + tid;
        int d = i >> 6, k = i & 63;
        Wt[k][d] = W[d * 128 + k];
    }
    size_t rbase = (size_t)blockIdx.x * 32;
    for (int it = 0; it < 16; it++) {
        int i = it * 128 + tid;
        int r = i >> 6, k = i & 63;
        ((float*)loc4)[r * 64 + k] = loc_emb[(rbase + r) * 64 + k];
    }
    __syncthreads();
    int d = tid;
    for (int rb = 0; rb < 4; rb++) {
        float acc[8] = {0, 0, 0, 0, 0, 0, 0, 0};
        #pragma unroll
        for (int k4 = 0; k4 < 16; k4++) {
            float w0 = Wt[k4 * 4 + 0][d], w1 = Wt[k4 * 4 + 1][d];
            float w2 = Wt[k4 * 4 + 2][d], w3 = Wt[k4 * 4 + 3][d];
            #pragma unroll
            for (int r8 = 0; r8 < 8; r8++) {
                float4 lv = loc4[rb * 8 + r8][k4];
                acc[r8] += w0 * lv.x + w1 * lv.y + w2 * lv.z + w3 * lv.w;
            }
        }
        #pragma unroll
        for (int r8 = 0; r8 < 8; r8++)
            d_Ah[(rbase + rb * 8 + r8) * 128 + d] = __float2half_rn(acc[r8]);
    }
}

// ---------------- K6: final output ----------------
__device__ __forceinline__ float ftanh(float v) {
    float a = fabsf(v);
    if (a < 0.5f) {
        float s = v * v;
        return v * (1.f + s * (-0.333333333f + s * (0.133333333f + s * (-0.053968254f))));
    }
    return tanhf(v);
}

__device__ __forceinline__ float2 h2f(unsigned w) {
    return __half22float2(*(const __half2*)&w);
}

__global__ void k_out(const float* __restrict__ W, float* __restrict__ out, int n) {
    int row = (int)((blockIdx.x * blockDim.x + threadIdx.x) >> 5);
    int lane = threadIdx.x & 31;
    if (row >= n) return;
    float4* o4 = (float4*)(out + (size_t)row * 128) + lane;
    unsigned nu = d_nuniq;
    if ((unsigned)row >= nu) {
        __stcs(o4, make_float4(0.f, 0.f, 0.f, 0.f));
        return;
    }
    uint2 g2 = d_g2[row];
    unsigned h = g2.x;
    unsigned c = g2.y >> 26;
    unsigned xx = h % MCONST, tt = h / MCONST;   // constant-divisor -> fast mul

    uint2 ar = *(const uint2*)&d_Ah[(size_t)xx * 128 + lane * 4];     // 4 halves
    float4 bt = *(const float4*)&d_Bb[tt * 128 + lane * 4];           // includes bias
    float2 a01 = h2f(ar.x), a23 = h2f(ar.y);

    float4 uc;
    if (c == 1) {
        unsigned uu = g2.y & CMASK;
        uint2 cr = *(const uint2*)&d_Ch[(size_t)uu * 128 + lane * 4];
        float2 c01 = h2f(cr.x), c23 = h2f(cr.y);
        uc = make_float4(c01.x, c01.y, c23.x, c23.y);
    } else {
        float inv = 1.f / (float)c;
        float um = d_usum[(size_t)row * 32 + lane] * inv;
        float a0 = 0, a1 = 0, a2 = 0, a3 = 0;
        int dbase = lane * 4;
        #pragma unroll
        for (int k = 0; k < 32; k++) {
            float umk = __shfl_sync(0xffffffffu, um, k);
            a0 += W[(dbase + 0) * 128 + 96 + k] * umk;
            a1 += W[(dbase + 1) * 128 + 96 + k] * umk;
            a2 += W[(dbase + 2) * 128 + 96 + k] * umk;
            a3 += W[(dbase + 3) * 128 + 96 + k] * umk;
        }
        uc = make_float4(a0, a1, a2, a3);
    }
    float4 r;
    r.x = ftanh(a01.x + bt.x + uc.x);
    r.y = ftanh(a01.y + bt.y + uc.y);
    r.z = ftanh(a23.x + bt.z + uc.z);
    r.w = ftanh(a23.y + bt.w + uc.w);
    __stcs(o4, r);
}

// ---------------- host launch ----------------
extern "C" void kernel_launch(void* const* d_in, const int* in_sizes, int n_in,
                              void* d_out, int out_size) {
    const float* loc_emb  = (const float*)d_in[0];
    const float* time_emb = (const float*)d_in[1];
    const float* user_emb = (const float*)d_in[2];
    const float* W        = (const float*)d_in[3];
    const float* b        = (const float*)d_in[4];
    const int*   x        = (const int*)d_in[5];
    const int*   t        = (const int*)d_in[6];
    const int*   u        = (const int*)d_in[7];
    int n       = in_sizes[5];              // 1,000,000 rows
    int nUsers1 = in_sizes[2] / 32;         // 50,001
    int rows    = out_size / 128;           // output rows (== n)

    k_zero_cnt<<<(HMAX / 4 + 255) / 256, 256>>>();
    k_count<<<(n + 255) / 256, 256>>>(x, t, u, n);
    k_tilesum<<<NTILES, 256>>>();
    k_scan<<<1, 1024>>>();
    k_emit<<<NTILES, 256>>>();
    k_accum<<<(n + 255) / 256, 256>>>(x, t, u, user_emb, n);
    // precomputes last so A/C stay hot in L2 for k_out
    kp_B<<<NTIMES, 128>>>(W, time_emb, b);
    kp_C<<<nUsers1, 128>>>(W, user_emb);
    kp_A<<<NLOCS / 32, 128>>>(W, loc_emb);
    k_out<<<(rows * 32 + 255) / 256, 256>>>(W, (float*)d_out, rows);
}